// round 15
// baseline (speedup 1.0000x reference)
#include <cuda_runtime.h>
#include <cstdint>

namespace {

constexpr int NB = 4, DIN = 4000, DE = 128, DB = 8;
constexpr int KD = DIN + DE + DB;   // 4136
constexpr int MD = 512;
constexpr float ALPHA = 0.3f;
constexpr int NSLAB = 130;          // 32-K images: 129 real + 1 zero-padded tail
constexpr int NPAIR = 65;           // main consumes image pairs (64 K per stage)
constexpr int IMG_BYTES   = 8192;
constexpr int STAGE_BYTES = 4 * IMG_BYTES;     // A0 A1 B0 B1 = 32KB
constexpr int NBUF = 3;
constexpr int SMEM_MAIN = NBUF * STAGE_BYTES;  // 96KB

__device__ __align__(16) uint8_t g_Afrag[(size_t)NB * 32 * NSLAB * IMG_BYTES]; // 136MB
__device__ __align__(16) uint8_t g_Wfrag[(size_t)NB * 4  * NSLAB * IMG_BYTES]; // 17MB

__device__ __forceinline__ uint32_t h2pack(float lo, float hi) {  // lo -> low 16 bits
    uint32_t u;
    asm("cvt.rn.f16x2.f32 %0, %1, %2;" : "=r"(u) : "f"(hi), "f"(lo));
    return u;
}
__device__ __forceinline__ uint32_t smem_u32(const void* p) {
    uint32_t a;
    asm("{ .reg .u64 t; cvta.to.shared.u64 t, %1; cvt.u32.u64 %0, t; }" : "=r"(a) : "l"(p));
    return a;
}
__device__ __forceinline__ void sts32(uint32_t a, uint32_t v) {
    asm volatile("st.shared.b32 [%0], %1;" :: "r"(a), "r"(v) : "memory");
}
__device__ __forceinline__ void sts64(uint32_t a, uint32_t v0, uint32_t v1) {
    asm volatile("st.shared.v2.b32 [%0], {%1,%2};" :: "r"(a), "r"(v0), "r"(v1) : "memory");
}
__device__ __forceinline__ void lds128(uint32_t a, uint32_t* r) {
    asm volatile("ld.shared.v4.b32 {%0,%1,%2,%3}, [%4];"
                 : "=r"(r[0]), "=r"(r[1]), "=r"(r[2]), "=r"(r[3]) : "r"(a));
}
__device__ __forceinline__ void mma16(float* d, const uint32_t* a, uint32_t b0, uint32_t b1) {
    asm volatile(
        "mma.sync.aligned.m16n8k16.row.col.f32.f16.f16.f32 "
        "{%0,%1,%2,%3}, {%4,%5,%6,%7}, {%8,%9}, {%0,%1,%2,%3};"
        : "+f"(d[0]), "+f"(d[1]), "+f"(d[2]), "+f"(d[3])
        : "r"(a[0]), "r"(a[1]), "r"(a[2]), "r"(a[3]), "r"(b0), "r"(b1));
}
__device__ __forceinline__ void cp16(uint32_t saddr, const void* gaddr) {
    asm volatile("cp.async.cg.shared.global [%0], [%1], 16;"
                 :: "r"(saddr), "l"(gaddr) : "memory");
}
#define CP_COMMIT() asm volatile("cp.async.commit_group;" ::: "memory")
#define CP_WAIT1()  asm volatile("cp.async.wait_group 1;" ::: "memory")

// ======================= merged prep: A tiles (y<32) + W tiles (y>=32) =======================
// (unchanged — known-good, runs at ~HBM roofline)
__global__ void __launch_bounds__(256)
prep_all(const float* __restrict__ x, const uint32_t* __restrict__ mask,
         const float* __restrict__ embed, const float* __restrict__ batches,
         const float* __restrict__ mean, const float* __restrict__ W)
{
    __shared__ uint32_t sf[2048];    // 8KB image
    const int s  = blockIdx.x;
    const int y  = blockIdx.y;
    const int b  = blockIdx.z;
    const int t  = threadIdx.x;
    const uint32_t base = smem_u32(sf);
    const int k0 = s * 32;

    if (y < 32) {
        // ---------------- A tile ----------------
        const int rB = y * 128;
        if (s < 129) {
            float4 xlo[2], xhi[2], mu[2];
            uint4  mlo[2], mhi[2];
            const bool xreg = (s < 125);
#pragma unroll
            for (int p = 0; p < 2; p++) {
                const int unit = p * 256 + t;
                const int q = unit & 7, pr = unit >> 3;
                const int mf = pr >> 3, rr = pr & 7;
                const int rlo = rB + mf * 16 + rr, rhi = rlo + 8;
                if (xreg) {
                    const int gk = k0 + q * 4;
                    const size_t glo = (size_t)rlo * (NB * DIN) + (size_t)b * DIN + gk;
                    const size_t ghi = (size_t)rhi * (NB * DIN) + (size_t)b * DIN + gk;
                    xlo[p] = *reinterpret_cast<const float4*>(x + glo);
                    xhi[p] = *reinterpret_cast<const float4*>(x + ghi);
                    mlo[p] = *reinterpret_cast<const uint4*>(mask + glo);
                    mhi[p] = *reinterpret_cast<const uint4*>(mask + ghi);
                    mu[p]  = *reinterpret_cast<const float4*>(mean + b * DIN + gk);
                } else {
                    const int e = k0 - DIN + q * 4;
                    xlo[p] = *reinterpret_cast<const float4*>(
                        embed + (size_t)rlo * (NB * DE) + b * DE + e);
                    xhi[p] = *reinterpret_cast<const float4*>(
                        embed + (size_t)rhi * (NB * DE) + b * DE + e);
                }
            }
#pragma unroll
            for (int p = 0; p < 2; p++) {
                const int unit = p * 256 + t;
                const int q = unit & 7, pr = unit >> 3;
                const int mf = pr >> 3, rr = pr & 7;
                float vl[4], vh[4];
                if (xreg) {
                    vl[0] = mlo[p].x ? xlo[p].x - mu[p].x : 0.f;
                    vl[1] = mlo[p].y ? xlo[p].y - mu[p].y : 0.f;
                    vl[2] = mlo[p].z ? xlo[p].z - mu[p].z : 0.f;
                    vl[3] = mlo[p].w ? xlo[p].w - mu[p].w : 0.f;
                    vh[0] = mhi[p].x ? xhi[p].x - mu[p].x : 0.f;
                    vh[1] = mhi[p].y ? xhi[p].y - mu[p].y : 0.f;
                    vh[2] = mhi[p].z ? xhi[p].z - mu[p].z : 0.f;
                    vh[3] = mhi[p].w ? xhi[p].w - mu[p].w : 0.f;
                } else {
                    vl[0] = xlo[p].x; vl[1] = xlo[p].y; vl[2] = xlo[p].z; vl[3] = xlo[p].w;
                    vh[0] = xhi[p].x; vh[1] = xhi[p].y; vh[2] = xhi[p].z; vh[3] = xhi[p].w;
                }
                const uint32_t h0 = h2pack(vl[0], vl[1]);
                const uint32_t h1 = h2pack(vh[0], vh[1]);
                const uint32_t h2 = h2pack(vl[2], vl[3]);
                const uint32_t h3 = h2pack(vh[2], vh[3]);
                const int ks = q >> 2, hi = (q >> 1) & 1, pl = 2 * (q & 1);
                const uint32_t s0 = (uint32_t)((rr * 4 + pl) ^ ks);
                const uint32_t s1 = (uint32_t)((rr * 4 + pl + 1) ^ ks);
                const uint32_t fb = base + (uint32_t)((ks * 8 + mf) * 32) * 16 + hi * 8;
                sts64(fb + s0 * 16, h0, h1);
                sts64(fb + s1 * 16, h2, h3);
            }
        } else {
            float4 blo, bhi;
            int mf = 0, rr = 0, q = 0;
            if (t < 128) {
                const int pr = t >> 1;
                q = t & 1; mf = pr >> 3; rr = pr & 7;
                const int rlo = rB + mf * 16 + rr;
                blo = *reinterpret_cast<const float4*>(batches + (size_t)rlo * DB + q * 4);
                bhi = *reinterpret_cast<const float4*>(batches + (size_t)(rlo + 8) * DB + q * 4);
            }
            for (int i = t; i < 2048; i += 256) sf[i] = 0;
            __syncthreads();
            if (t < 128) {
                const uint32_t h0 = h2pack(blo.x, blo.y);
                const uint32_t h1 = h2pack(bhi.x, bhi.y);
                const uint32_t h2 = h2pack(blo.z, blo.w);
                const uint32_t h3 = h2pack(bhi.z, bhi.w);
                const int pl = 2 * q;
                const uint32_t fb = base + (uint32_t)(mf * 32) * 16;
                sts64(fb + (uint32_t)(rr * 4 + pl) * 16, h0, h1);
                sts64(fb + (uint32_t)(rr * 4 + pl + 1) * 16, h2, h3);
            }
        }
        __syncthreads();
        uint4* dst = reinterpret_cast<uint4*>(
            g_Afrag + ((size_t)(b * 32 + y) * NSLAB + s) * IMG_BYTES);
        const uint4* src = reinterpret_cast<const uint4*>(sf);
        dst[t] = src[t];
        dst[256 + t] = src[256 + t];
    } else {
        // ---------------- W tile ----------------
        const int cbi = y - 32;
        const float* Wb = W + (size_t)b * KD * MD + cbi * 128;
        if (s < 129) {
            float4 w0[2], w1[2];
#pragma unroll
            for (int p = 0; p < 2; p++) {
                const int unit = p * 256 + t;
                const int kp = unit >> 5, n0 = (unit & 31) * 4;
                const int k = k0 + kp * 2;
                w0[p] = *reinterpret_cast<const float4*>(Wb + (size_t)k * MD + n0);
                w1[p] = *reinterpret_cast<const float4*>(Wb + (size_t)(k + 1) * MD + n0);
            }
#pragma unroll
            for (int p = 0; p < 2; p++) {
                const int unit = p * 256 + t;
                const int kp = unit >> 5, n0 = (unit & 31) * 4;
                const int ks = kp >> 3, kpi = kp & 7;
                const int tk = kpi & 3, hi = kpi >> 2;
                const uint32_t h[4] = {h2pack(w0[p].x, w1[p].x), h2pack(w0[p].y, w1[p].y),
                                       h2pack(w0[p].z, w1[p].z), h2pack(w0[p].w, w1[p].w)};
#pragma unroll
                for (int i = 0; i < 4; i++) {
                    const int n = n0 + i, col = n & 7, nf = n >> 3, np = nf >> 1;
                    const int reg = (nf & 1) * 2 + hi;
                    const int slot = (col * 4 + tk) ^ np;
                    sts32(base + (uint32_t)(((ks * 8 + np) * 32 + slot) * 16 + reg * 4),
                          h[i]);
                }
            }
        } else {
            float4 w0, w1;
            int kp = 0, n0 = 0;
            if (t < 128) {
                kp = t >> 5; n0 = (t & 31) * 4;
                const int k = k0 + kp * 2;
                w0 = *reinterpret_cast<const float4*>(Wb + (size_t)k * MD + n0);
                w1 = *reinterpret_cast<const float4*>(Wb + (size_t)(k + 1) * MD + n0);
            }
            for (int i = t; i < 2048; i += 256) sf[i] = 0;
            __syncthreads();
            if (t < 128) {
                const int tk = kp & 3;
                const uint32_t h[4] = {h2pack(w0.x, w1.x), h2pack(w0.y, w1.y),
                                       h2pack(w0.z, w1.z), h2pack(w0.w, w1.w)};
#pragma unroll
                for (int i = 0; i < 4; i++) {
                    const int n = n0 + i, col = n & 7, nf = n >> 3, np = nf >> 1;
                    const int reg = (nf & 1) * 2;
                    const int slot = (col * 4 + tk) ^ np;
                    sts32(base + (uint32_t)((np * 32 + slot) * 16 + reg * 4), h[i]);
                }
            }
        }
        __syncthreads();
        uint4* dst = reinterpret_cast<uint4*>(
            g_Wfrag + ((size_t)(b * 4 + cbi) * NSLAB + s) * IMG_BYTES);
        const uint4* src = reinterpret_cast<const uint4*>(sf);
        dst[t] = src[t];
        dst[256 + t] = src[256 + t];
    }
}

// ===== main: 64-K pair stages, 3-buffer ring, quarter-granularity cp interleave =====
__global__ void __launch_bounds__(256, 2)
ib_main(const float* __restrict__ bias, float* __restrict__ out)
{
    extern __shared__ char smem[];
    const uint32_t sb = smem_u32(smem);
    const int t    = threadIdx.x;
    const int lane = t & 31;
    const int wid  = t >> 5;
    const int wm   = wid & 3;        // 32 rows each
    const int wn   = wid >> 2;       // 64 cols each
    const int cbi  = blockIdx.x;
    const int rt   = blockIdx.y;
    const int b    = blockIdx.z;
    const int rB   = rt * 128;
    const int cB   = cbi * 128;

    const uint8_t* gA = g_Afrag + (size_t)(b * 32 + rt) * NSLAB * IMG_BYTES;
    const uint8_t* gW = g_Wfrag + (size_t)(b * 4 + cbi) * NSLAB * IMG_BYTES;

    float acc[2][8][4];
#pragma unroll
    for (int m = 0; m < 2; m++)
#pragma unroll
        for (int n = 0; n < 8; n++)
#pragma unroll
            for (int q = 0; q < 4; q++) acc[m][n][q] = 0.f;

    // stage layout: [A(img0) 8K][A(img1) 8K][B(img0) 8K][B(img1) 8K]
    // quarter qt = 0..3 copies 2 x 4KB chunks: qt 0,1 -> A chunks, qt 2,3 -> B chunks
    auto cp_quarter = [&](int p, int qt) {
        const uint32_t buf = sb + (uint32_t)((p % NBUF) * STAGE_BYTES);
        const uint32_t off = (uint32_t)t * 16;
        const int half = qt >> 1;                 // 0 = A images, 1 = B images
        const int c0 = (qt & 1) * 2;              // chunk 0..3 within half
        const uint8_t* src = (half == 0 ? gA : gW) + (size_t)(2 * p) * IMG_BYTES;
        const uint32_t dbase = buf + (uint32_t)half * 2 * IMG_BYTES;
#pragma unroll
        for (int c = c0; c < c0 + 2; c++)
            cp16(dbase + c * 4096 + off, src + c * 4096 + off);
    };

    auto consume = [&](uint32_t buf, int img, int ks) {
        const uint32_t abase = buf + (uint32_t)img * IMG_BYTES;
        const uint32_t bbase = buf + 2 * IMG_BYTES + (uint32_t)img * IMG_BYTES;
        uint32_t afr[2][4], bfr[4][4];
#pragma unroll
        for (int m = 0; m < 2; m++)
            lds128(abase + (uint32_t)(((ks * 8 + wm * 2 + m) * 32 + (lane ^ ks)) * 16),
                   afr[m]);
#pragma unroll
        for (int pp = 0; pp < 4; pp++) {
            const int np = wn * 4 + pp;
            lds128(bbase + (uint32_t)(((ks * 8 + np) * 32 + (lane ^ np)) * 16),
                   bfr[pp]);
        }
#pragma unroll
        for (int m = 0; m < 2; m++)
#pragma unroll
            for (int pp = 0; pp < 4; pp++) {
                mma16(acc[m][2 * pp],     afr[m], bfr[pp][0], bfr[pp][1]);
                mma16(acc[m][2 * pp + 1], afr[m], bfr[pp][2], bfr[pp][3]);
            }
    };

    // prologue: 2 pair-stages in flight
#pragma unroll
    for (int qt = 0; qt < 4; qt++) cp_quarter(0, qt);
    CP_COMMIT();
#pragma unroll
    for (int qt = 0; qt < 4; qt++) cp_quarter(1, qt);
    CP_COMMIT();

    for (int p = 0; p < NPAIR; p++) {
        CP_WAIT1();               // stage p resident (<=1 newer committed group pending)
        __syncthreads();          // all warps done with stage p-1's buffer
        const uint32_t buf = sb + (uint32_t)((p % NBUF) * STAGE_BYTES);
        const bool pf = (p + 2 < NPAIR);
        // one cp quarter (2 x cp16) after each consume step: even LSU pressure
        consume(buf, 0, 0);
        if (pf) cp_quarter(p + 2, 0);
        consume(buf, 0, 1);
        if (pf) cp_quarter(p + 2, 1);
        consume(buf, 1, 0);
        if (pf) cp_quarter(p + 2, 2);
        consume(buf, 1, 1);
        if (pf) cp_quarter(p + 2, 3);
        CP_COMMIT();              // exactly one group per iteration
    }

    // -------- epilogue: bias + LeakyReLU --------
    const int g  = lane >> 2;
    const int tq = lane & 3;
#pragma unroll
    for (int m = 0; m < 2; m++) {
        const int r0 = rB + wm * 32 + m * 16 + g;
#pragma unroll
        for (int nf = 0; nf < 8; nf++) {
            const int col = cB + wn * 64 + nf * 8 + tq * 2;
            const float2 bv = *reinterpret_cast<const float2*>(bias + b * MD + col);
            float v0 = acc[m][nf][0] + bv.x;
            float v1 = acc[m][nf][1] + bv.y;
            float v2 = acc[m][nf][2] + bv.x;
            float v3 = acc[m][nf][3] + bv.y;
            v0 = (v0 >= 0.f) ? v0 : ALPHA * v0;
            v1 = (v1 >= 0.f) ? v1 : ALPHA * v1;
            v2 = (v2 >= 0.f) ? v2 : ALPHA * v2;
            v3 = (v3 >= 0.f) ? v3 : ALPHA * v3;
            *reinterpret_cast<float2*>(out + (size_t)r0 * (NB * MD) + b * MD + col)
                = make_float2(v0, v1);
            *reinterpret_cast<float2*>(out + (size_t)(r0 + 8) * (NB * MD) + b * MD + col)
                = make_float2(v2, v3);
        }
    }
}

} // namespace

extern "C" void kernel_launch(void* const* d_in, const int* in_sizes, int n_in,
                              void* d_out, int out_size)
{
    const float*    x       = (const float*)d_in[0];
    const uint32_t* mask    = (const uint32_t*)d_in[1];
    const float*    embed   = (const float*)d_in[2];
    const float*    batches = (const float*)d_in[3];
    const float*    mean    = (const float*)d_in[4];
    const float*    W       = (const float*)d_in[5];
    const float*    bias    = (const float*)d_in[6];
    float*          out     = (float*)d_out;

    prep_all<<<dim3(NSLAB, 36, NB), 256>>>(x, mask, embed, batches, mean, W);

    cudaFuncSetAttribute(ib_main, cudaFuncAttributeMaxDynamicSharedMemorySize, SMEM_MAIN);
    ib_main<<<dim3(4, 32, NB), 256, SMEM_MAIN>>>(bias, out);
}

// round 16
// speedup vs baseline: 1.4699x; 1.4699x over previous
#include <cuda_runtime.h>
#include <cstdint>

namespace {

constexpr int NB = 4, DIN = 4000, DE = 128, DB = 8;
constexpr int KD = DIN + DE + DB;   // 4136
constexpr int MD = 512;
constexpr float ALPHA = 0.3f;
constexpr int NSLAB = 130;          // 32-K images: 129 real + 1 zero-padded tail
constexpr int NPAIR = 65;           // main consumes image pairs (64 K per stage)
constexpr int IMG_BYTES   = 8192;
constexpr int STAGE_BYTES = 4 * IMG_BYTES;     // A0 A1 B0 B1 = 32KB
constexpr int NBUF = 3;
constexpr int SMEM_MAIN = NBUF * STAGE_BYTES;  // 96KB

__device__ __align__(16) uint8_t g_Afrag[(size_t)NB * 32 * NSLAB * IMG_BYTES]; // 136MB
__device__ __align__(16) uint8_t g_Wfrag[(size_t)NB * 4  * NSLAB * IMG_BYTES]; // 17MB

__device__ __forceinline__ uint32_t h2pack(float lo, float hi) {  // lo -> low 16 bits
    uint32_t u;
    asm("cvt.rn.f16x2.f32 %0, %1, %2;" : "=r"(u) : "f"(hi), "f"(lo));
    return u;
}
__device__ __forceinline__ uint32_t smem_u32(const void* p) {
    uint32_t a;
    asm("{ .reg .u64 t; cvta.to.shared.u64 t, %1; cvt.u32.u64 %0, t; }" : "=r"(a) : "l"(p));
    return a;
}
__device__ __forceinline__ void sts32(uint32_t a, uint32_t v) {
    asm volatile("st.shared.b32 [%0], %1;" :: "r"(a), "r"(v) : "memory");
}
__device__ __forceinline__ void sts64(uint32_t a, uint32_t v0, uint32_t v1) {
    asm volatile("st.shared.v2.b32 [%0], {%1,%2};" :: "r"(a), "r"(v0), "r"(v1) : "memory");
}
__device__ __forceinline__ void lds128(uint32_t a, uint32_t* r) {
    asm volatile("ld.shared.v4.b32 {%0,%1,%2,%3}, [%4];"
                 : "=r"(r[0]), "=r"(r[1]), "=r"(r[2]), "=r"(r[3]) : "r"(a));
}
__device__ __forceinline__ void mma16(float* d, const uint32_t* a, uint32_t b0, uint32_t b1) {
    asm volatile(
        "mma.sync.aligned.m16n8k16.row.col.f32.f16.f16.f32 "
        "{%0,%1,%2,%3}, {%4,%5,%6,%7}, {%8,%9}, {%0,%1,%2,%3};"
        : "+f"(d[0]), "+f"(d[1]), "+f"(d[2]), "+f"(d[3])
        : "r"(a[0]), "r"(a[1]), "r"(a[2]), "r"(a[3]), "r"(b0), "r"(b1));
}
__device__ __forceinline__ void cp16(uint32_t saddr, const void* gaddr) {
    asm volatile("cp.async.cg.shared.global [%0], [%1], 16;"
                 :: "r"(saddr), "l"(gaddr) : "memory");
}
#define CP_COMMIT() asm volatile("cp.async.commit_group;" ::: "memory")
#define CP_WAIT1()  asm volatile("cp.async.wait_group 1;" ::: "memory")

// ======================= merged prep: A tiles (y<32) + W tiles (y>=32) =======================
// (known-good, runs at ~HBM roofline)
__global__ void __launch_bounds__(256)
prep_all(const float* __restrict__ x, const uint32_t* __restrict__ mask,
         const float* __restrict__ embed, const float* __restrict__ batches,
         const float* __restrict__ mean, const float* __restrict__ W)
{
    __shared__ uint32_t sf[2048];    // 8KB image
    const int s  = blockIdx.x;
    const int y  = blockIdx.y;
    const int b  = blockIdx.z;
    const int t  = threadIdx.x;
    const uint32_t base = smem_u32(sf);
    const int k0 = s * 32;

    if (y < 32) {
        // ---------------- A tile ----------------
        const int rB = y * 128;
        if (s < 129) {
            float4 xlo[2], xhi[2], mu[2];
            uint4  mlo[2], mhi[2];
            const bool xreg = (s < 125);
#pragma unroll
            for (int p = 0; p < 2; p++) {
                const int unit = p * 256 + t;
                const int q = unit & 7, pr = unit >> 3;
                const int mf = pr >> 3, rr = pr & 7;
                const int rlo = rB + mf * 16 + rr, rhi = rlo + 8;
                if (xreg) {
                    const int gk = k0 + q * 4;
                    const size_t glo = (size_t)rlo * (NB * DIN) + (size_t)b * DIN + gk;
                    const size_t ghi = (size_t)rhi * (NB * DIN) + (size_t)b * DIN + gk;
                    xlo[p] = *reinterpret_cast<const float4*>(x + glo);
                    xhi[p] = *reinterpret_cast<const float4*>(x + ghi);
                    mlo[p] = *reinterpret_cast<const uint4*>(mask + glo);
                    mhi[p] = *reinterpret_cast<const uint4*>(mask + ghi);
                    mu[p]  = *reinterpret_cast<const float4*>(mean + b * DIN + gk);
                } else {
                    const int e = k0 - DIN + q * 4;
                    xlo[p] = *reinterpret_cast<const float4*>(
                        embed + (size_t)rlo * (NB * DE) + b * DE + e);
                    xhi[p] = *reinterpret_cast<const float4*>(
                        embed + (size_t)rhi * (NB * DE) + b * DE + e);
                }
            }
#pragma unroll
            for (int p = 0; p < 2; p++) {
                const int unit = p * 256 + t;
                const int q = unit & 7, pr = unit >> 3;
                const int mf = pr >> 3, rr = pr & 7;
                float vl[4], vh[4];
                if (xreg) {
                    vl[0] = mlo[p].x ? xlo[p].x - mu[p].x : 0.f;
                    vl[1] = mlo[p].y ? xlo[p].y - mu[p].y : 0.f;
                    vl[2] = mlo[p].z ? xlo[p].z - mu[p].z : 0.f;
                    vl[3] = mlo[p].w ? xlo[p].w - mu[p].w : 0.f;
                    vh[0] = mhi[p].x ? xhi[p].x - mu[p].x : 0.f;
                    vh[1] = mhi[p].y ? xhi[p].y - mu[p].y : 0.f;
                    vh[2] = mhi[p].z ? xhi[p].z - mu[p].z : 0.f;
                    vh[3] = mhi[p].w ? xhi[p].w - mu[p].w : 0.f;
                } else {
                    vl[0] = xlo[p].x; vl[1] = xlo[p].y; vl[2] = xlo[p].z; vl[3] = xlo[p].w;
                    vh[0] = xhi[p].x; vh[1] = xhi[p].y; vh[2] = xhi[p].z; vh[3] = xhi[p].w;
                }
                const uint32_t h0 = h2pack(vl[0], vl[1]);
                const uint32_t h1 = h2pack(vh[0], vh[1]);
                const uint32_t h2 = h2pack(vl[2], vl[3]);
                const uint32_t h3 = h2pack(vh[2], vh[3]);
                const int ks = q >> 2, hi = (q >> 1) & 1, pl = 2 * (q & 1);
                const uint32_t s0 = (uint32_t)((rr * 4 + pl) ^ ks);
                const uint32_t s1 = (uint32_t)((rr * 4 + pl + 1) ^ ks);
                const uint32_t fb = base + (uint32_t)((ks * 8 + mf) * 32) * 16 + hi * 8;
                sts64(fb + s0 * 16, h0, h1);
                sts64(fb + s1 * 16, h2, h3);
            }
        } else {
            float4 blo, bhi;
            int mf = 0, rr = 0, q = 0;
            if (t < 128) {
                const int pr = t >> 1;
                q = t & 1; mf = pr >> 3; rr = pr & 7;
                const int rlo = rB + mf * 16 + rr;
                blo = *reinterpret_cast<const float4*>(batches + (size_t)rlo * DB + q * 4);
                bhi = *reinterpret_cast<const float4*>(batches + (size_t)(rlo + 8) * DB + q * 4);
            }
            for (int i = t; i < 2048; i += 256) sf[i] = 0;
            __syncthreads();
            if (t < 128) {
                const uint32_t h0 = h2pack(blo.x, blo.y);
                const uint32_t h1 = h2pack(bhi.x, bhi.y);
                const uint32_t h2 = h2pack(blo.z, blo.w);
                const uint32_t h3 = h2pack(bhi.z, bhi.w);
                const int pl = 2 * q;
                const uint32_t fb = base + (uint32_t)(mf * 32) * 16;
                sts64(fb + (uint32_t)(rr * 4 + pl) * 16, h0, h1);
                sts64(fb + (uint32_t)(rr * 4 + pl + 1) * 16, h2, h3);
            }
        }
        __syncthreads();
        uint4* dst = reinterpret_cast<uint4*>(
            g_Afrag + ((size_t)(b * 32 + y) * NSLAB + s) * IMG_BYTES);
        const uint4* src = reinterpret_cast<const uint4*>(sf);
        dst[t] = src[t];
        dst[256 + t] = src[256 + t];
    } else {
        // ---------------- W tile ----------------
        const int cbi = y - 32;
        const float* Wb = W + (size_t)b * KD * MD + cbi * 128;
        if (s < 129) {
            float4 w0[2], w1[2];
#pragma unroll
            for (int p = 0; p < 2; p++) {
                const int unit = p * 256 + t;
                const int kp = unit >> 5, n0 = (unit & 31) * 4;
                const int k = k0 + kp * 2;
                w0[p] = *reinterpret_cast<const float4*>(Wb + (size_t)k * MD + n0);
                w1[p] = *reinterpret_cast<const float4*>(Wb + (size_t)(k + 1) * MD + n0);
            }
#pragma unroll
            for (int p = 0; p < 2; p++) {
                const int unit = p * 256 + t;
                const int kp = unit >> 5, n0 = (unit & 31) * 4;
                const int ks = kp >> 3, kpi = kp & 7;
                const int tk = kpi & 3, hi = kpi >> 2;
                const uint32_t h[4] = {h2pack(w0[p].x, w1[p].x), h2pack(w0[p].y, w1[p].y),
                                       h2pack(w0[p].z, w1[p].z), h2pack(w0[p].w, w1[p].w)};
#pragma unroll
                for (int i = 0; i < 4; i++) {
                    const int n = n0 + i, col = n & 7, nf = n >> 3, np = nf >> 1;
                    const int reg = (nf & 1) * 2 + hi;
                    const int slot = (col * 4 + tk) ^ np;
                    sts32(base + (uint32_t)(((ks * 8 + np) * 32 + slot) * 16 + reg * 4),
                          h[i]);
                }
            }
        } else {
            float4 w0, w1;
            int kp = 0, n0 = 0;
            if (t < 128) {
                kp = t >> 5; n0 = (t & 31) * 4;
                const int k = k0 + kp * 2;
                w0 = *reinterpret_cast<const float4*>(Wb + (size_t)k * MD + n0);
                w1 = *reinterpret_cast<const float4*>(Wb + (size_t)(k + 1) * MD + n0);
            }
            for (int i = t; i < 2048; i += 256) sf[i] = 0;
            __syncthreads();
            if (t < 128) {
                const int tk = kp & 3;
                const uint32_t h[4] = {h2pack(w0.x, w1.x), h2pack(w0.y, w1.y),
                                       h2pack(w0.z, w1.z), h2pack(w0.w, w1.w)};
#pragma unroll
                for (int i = 0; i < 4; i++) {
                    const int n = n0 + i, col = n & 7, nf = n >> 3, np = nf >> 1;
                    const int reg = (nf & 1) * 2;
                    const int slot = (col * 4 + tk) ^ np;
                    sts32(base + (uint32_t)((np * 32 + slot) * 16 + reg * 4), h[i]);
                }
            }
        }
        __syncthreads();
        uint4* dst = reinterpret_cast<uint4*>(
            g_Wfrag + ((size_t)(b * 4 + cbi) * NSLAB + s) * IMG_BYTES);
        const uint4* src = reinterpret_cast<const uint4*>(sf);
        dst[t] = src[t];
        dst[256 + t] = src[256 + t];
    }
}

// ===== main: 64-K pair stages, 3-buffer cp.async ring, cp issue interleaved with MMA =====
__global__ void __launch_bounds__(256, 2)
ib_main(const float* __restrict__ bias, float* __restrict__ out)
{
    extern __shared__ char smem[];
    const uint32_t sb = smem_u32(smem);
    const int t    = threadIdx.x;
    const int lane = t & 31;
    const int wid  = t >> 5;
    const int wm   = wid & 3;        // 32 rows each
    const int wn   = wid >> 2;       // 64 cols each
    const int cbi  = blockIdx.x;
    const int rt   = blockIdx.y;
    const int b    = blockIdx.z;
    const int rB   = rt * 128;
    const int cB   = cbi * 128;

    const uint8_t* gA = g_Afrag + (size_t)(b * 32 + rt) * NSLAB * IMG_BYTES;
    const uint8_t* gW = g_Wfrag + (size_t)(b * 4 + cbi) * NSLAB * IMG_BYTES;

    float acc[2][8][4];
#pragma unroll
    for (int m = 0; m < 2; m++)
#pragma unroll
        for (int n = 0; n < 8; n++)
#pragma unroll
            for (int q = 0; q < 4; q++) acc[m][n][q] = 0.f;

    // stage layout: [A(img0) 8K][A(img1) 8K][B(img0) 8K][B(img1) 8K]
    auto cp_half = [&](int p, int half) {   // half 0 = A images, half 1 = B images
        const uint32_t buf = sb + (uint32_t)((p % NBUF) * STAGE_BYTES)
                           + (uint32_t)half * 2 * IMG_BYTES;
        const uint8_t* src = (half == 0 ? gA : gW) + (size_t)(2 * p) * IMG_BYTES;
        const uint32_t off = (uint32_t)t * 16;
#pragma unroll
        for (int c = 0; c < 4; c++)
            cp16(buf + c * 4096 + off, src + c * 4096 + off);
    };

    auto consume = [&](uint32_t buf, int img, int ks) {
        const uint32_t abase = buf + (uint32_t)img * IMG_BYTES;
        const uint32_t bbase = buf + 2 * IMG_BYTES + (uint32_t)img * IMG_BYTES;
        uint32_t afr[2][4], bfr[4][4];
#pragma unroll
        for (int m = 0; m < 2; m++)
            lds128(abase + (uint32_t)(((ks * 8 + wm * 2 + m) * 32 + (lane ^ ks)) * 16),
                   afr[m]);
#pragma unroll
        for (int pp = 0; pp < 4; pp++) {
            const int np = wn * 4 + pp;
            lds128(bbase + (uint32_t)(((ks * 8 + np) * 32 + (lane ^ np)) * 16),
                   bfr[pp]);
        }
#pragma unroll
        for (int m = 0; m < 2; m++)
#pragma unroll
            for (int pp = 0; pp < 4; pp++) {
                mma16(acc[m][2 * pp],     afr[m], bfr[pp][0], bfr[pp][1]);
                mma16(acc[m][2 * pp + 1], afr[m], bfr[pp][2], bfr[pp][3]);
            }
    };

    // prologue: 2 pair-stages in flight
    cp_half(0, 0); cp_half(0, 1); CP_COMMIT();
    cp_half(1, 0); cp_half(1, 1); CP_COMMIT();

    for (int p = 0; p < NPAIR; p++) {
        CP_WAIT1();               // stage p resident (<=1 newer group pending)
        __syncthreads();          // all warps done with stage p-1's buffer
        const uint32_t buf = sb + (uint32_t)((p % NBUF) * STAGE_BYTES);
        // interleave next-stage cp issue between consume steps (smooths LSU pressure)
        consume(buf, 0, 0);
        if (p + 2 < NPAIR) cp_half(p + 2, 0);
        consume(buf, 0, 1);
        if (p + 2 < NPAIR) cp_half(p + 2, 1);
        CP_COMMIT();              // exactly one group per iteration
        consume(buf, 1, 0);
        consume(buf, 1, 1);
    }

    // -------- epilogue: bias + LeakyReLU --------
    const int g  = lane >> 2;
    const int tq = lane & 3;
#pragma unroll
    for (int m = 0; m < 2; m++) {
        const int r0 = rB + wm * 32 + m * 16 + g;
#pragma unroll
        for (int nf = 0; nf < 8; nf++) {
            const int col = cB + wn * 64 + nf * 8 + tq * 2;
            const float2 bv = *reinterpret_cast<const float2*>(bias + b * MD + col);
            float v0 = acc[m][nf][0] + bv.x;
            float v1 = acc[m][nf][1] + bv.y;
            float v2 = acc[m][nf][2] + bv.x;
            float v3 = acc[m][nf][3] + bv.y;
            v0 = (v0 >= 0.f) ? v0 : ALPHA * v0;
            v1 = (v1 >= 0.f) ? v1 : ALPHA * v1;
            v2 = (v2 >= 0.f) ? v2 : ALPHA * v2;
            v3 = (v3 >= 0.f) ? v3 : ALPHA * v3;
            *reinterpret_cast<float2*>(out + (size_t)r0 * (NB * MD) + b * MD + col)
                = make_float2(v0, v1);
            *reinterpret_cast<float2*>(out + (size_t)(r0 + 8) * (NB * MD) + b * MD + col)
                = make_float2(v2, v3);
        }
    }
}

} // namespace

extern "C" void kernel_launch(void* const* d_in, const int* in_sizes, int n_in,
                              void* d_out, int out_size)
{
    const float*    x       = (const float*)d_in[0];
    const uint32_t* mask    = (const uint32_t*)d_in[1];
    const float*    embed   = (const float*)d_in[2];
    const float*    batches = (const float*)d_in[3];
    const float*    mean    = (const float*)d_in[4];
    const float*    W       = (const float*)d_in[5];
    const float*    bias    = (const float*)d_in[6];
    float*          out     = (float*)d_out;

    prep_all<<<dim3(NSLAB, 36, NB), 256>>>(x, mask, embed, batches, mean, W);

    cudaFuncSetAttribute(ib_main, cudaFuncAttributeMaxDynamicSharedMemorySize, SMEM_MAIN);
    ib_main<<<dim3(4, 32, NB), 256, SMEM_MAIN>>>(bias, out);
}

// round 17
// speedup vs baseline: 1.4881x; 1.0124x over previous
#include <cuda_runtime.h>
#include <cstdint>

namespace {

constexpr int NB = 4, DIN = 4000, DE = 128, DB = 8;
constexpr int KD = DIN + DE + DB;   // 4136
constexpr int MD = 512;
constexpr float ALPHA = 0.3f;
constexpr int NSLAB = 130;          // 32-K images: 129 real + 1 zero-padded tail
constexpr int NPAIR = 65;           // main consumes image pairs (64 K per stage)
constexpr int IMG_BYTES   = 8192;
constexpr int STAGE_BYTES = 4 * IMG_BYTES;     // A0 A1 B0 B1 = 32KB
constexpr int NBUF = 3;
constexpr int SMEM_MAIN = NBUF * STAGE_BYTES;  // 96KB

__device__ __align__(16) uint8_t g_Afrag[(size_t)NB * 32 * NSLAB * IMG_BYTES]; // 136MB
__device__ __align__(16) uint8_t g_Wfrag[(size_t)NB * 4  * NSLAB * IMG_BYTES]; // 17MB

__device__ __forceinline__ uint32_t h2pack(float lo, float hi) {  // lo -> low 16 bits
    uint32_t u;
    asm("cvt.rn.f16x2.f32 %0, %1, %2;" : "=r"(u) : "f"(hi), "f"(lo));
    return u;
}
__device__ __forceinline__ uint32_t smem_u32(const void* p) {
    uint32_t a;
    asm("{ .reg .u64 t; cvta.to.shared.u64 t, %1; cvt.u32.u64 %0, t; }" : "=r"(a) : "l"(p));
    return a;
}
__device__ __forceinline__ void sts32(uint32_t a, uint32_t v) {
    asm volatile("st.shared.b32 [%0], %1;" :: "r"(a), "r"(v) : "memory");
}
__device__ __forceinline__ void sts64(uint32_t a, uint32_t v0, uint32_t v1) {
    asm volatile("st.shared.v2.b32 [%0], {%1,%2};" :: "r"(a), "r"(v0), "r"(v1) : "memory");
}
__device__ __forceinline__ void lds128(uint32_t a, uint32_t* r) {
    asm volatile("ld.shared.v4.b32 {%0,%1,%2,%3}, [%4];"
                 : "=r"(r[0]), "=r"(r[1]), "=r"(r[2]), "=r"(r[3]) : "r"(a));
}
__device__ __forceinline__ void mma16(float* d, const uint32_t* a, uint32_t b0, uint32_t b1) {
    asm volatile(
        "mma.sync.aligned.m16n8k16.row.col.f32.f16.f16.f32 "
        "{%0,%1,%2,%3}, {%4,%5,%6,%7}, {%8,%9}, {%0,%1,%2,%3};"
        : "+f"(d[0]), "+f"(d[1]), "+f"(d[2]), "+f"(d[3])
        : "r"(a[0]), "r"(a[1]), "r"(a[2]), "r"(a[3]), "r"(b0), "r"(b1));
}
__device__ __forceinline__ void cp16(uint32_t saddr, const void* gaddr) {
    asm volatile("cp.async.cg.shared.global [%0], [%1], 16;"
                 :: "r"(saddr), "l"(gaddr) : "memory");
}
#define CP_COMMIT() asm volatile("cp.async.commit_group;" ::: "memory")
#define CP_WAIT1()  asm volatile("cp.async.wait_group 1;" ::: "memory")

// ======================= merged prep: A tiles (y<32) + W tiles (y>=32) =======================
// (UNCHANGED — known-good, runs at ~HBM roofline)
__global__ void __launch_bounds__(256)
prep_all(const float* __restrict__ x, const uint32_t* __restrict__ mask,
         const float* __restrict__ embed, const float* __restrict__ batches,
         const float* __restrict__ mean, const float* __restrict__ W)
{
    __shared__ uint32_t sf[2048];    // 8KB image
    const int s  = blockIdx.x;
    const int y  = blockIdx.y;
    const int b  = blockIdx.z;
    const int t  = threadIdx.x;
    const uint32_t base = smem_u32(sf);
    const int k0 = s * 32;

    if (y < 32) {
        // ---------------- A tile ----------------
        const int rB = y * 128;
        if (s < 129) {
            float4 xlo[2], xhi[2], mu[2];
            uint4  mlo[2], mhi[2];
            const bool xreg = (s < 125);
#pragma unroll
            for (int p = 0; p < 2; p++) {
                const int unit = p * 256 + t;
                const int q = unit & 7, pr = unit >> 3;
                const int mf = pr >> 3, rr = pr & 7;
                const int rlo = rB + mf * 16 + rr, rhi = rlo + 8;
                if (xreg) {
                    const int gk = k0 + q * 4;
                    const size_t glo = (size_t)rlo * (NB * DIN) + (size_t)b * DIN + gk;
                    const size_t ghi = (size_t)rhi * (NB * DIN) + (size_t)b * DIN + gk;
                    xlo[p] = *reinterpret_cast<const float4*>(x + glo);
                    xhi[p] = *reinterpret_cast<const float4*>(x + ghi);
                    mlo[p] = *reinterpret_cast<const uint4*>(mask + glo);
                    mhi[p] = *reinterpret_cast<const uint4*>(mask + ghi);
                    mu[p]  = *reinterpret_cast<const float4*>(mean + b * DIN + gk);
                } else {
                    const int e = k0 - DIN + q * 4;
                    xlo[p] = *reinterpret_cast<const float4*>(
                        embed + (size_t)rlo * (NB * DE) + b * DE + e);
                    xhi[p] = *reinterpret_cast<const float4*>(
                        embed + (size_t)rhi * (NB * DE) + b * DE + e);
                }
            }
#pragma unroll
            for (int p = 0; p < 2; p++) {
                const int unit = p * 256 + t;
                const int q = unit & 7, pr = unit >> 3;
                const int mf = pr >> 3, rr = pr & 7;
                float vl[4], vh[4];
                if (xreg) {
                    vl[0] = mlo[p].x ? xlo[p].x - mu[p].x : 0.f;
                    vl[1] = mlo[p].y ? xlo[p].y - mu[p].y : 0.f;
                    vl[2] = mlo[p].z ? xlo[p].z - mu[p].z : 0.f;
                    vl[3] = mlo[p].w ? xlo[p].w - mu[p].w : 0.f;
                    vh[0] = mhi[p].x ? xhi[p].x - mu[p].x : 0.f;
                    vh[1] = mhi[p].y ? xhi[p].y - mu[p].y : 0.f;
                    vh[2] = mhi[p].z ? xhi[p].z - mu[p].z : 0.f;
                    vh[3] = mhi[p].w ? xhi[p].w - mu[p].w : 0.f;
                } else {
                    vl[0] = xlo[p].x; vl[1] = xlo[p].y; vl[2] = xlo[p].z; vl[3] = xlo[p].w;
                    vh[0] = xhi[p].x; vh[1] = xhi[p].y; vh[2] = xhi[p].z; vh[3] = xhi[p].w;
                }
                const uint32_t h0 = h2pack(vl[0], vl[1]);
                const uint32_t h1 = h2pack(vh[0], vh[1]);
                const uint32_t h2 = h2pack(vl[2], vl[3]);
                const uint32_t h3 = h2pack(vh[2], vh[3]);
                const int ks = q >> 2, hi = (q >> 1) & 1, pl = 2 * (q & 1);
                const uint32_t s0 = (uint32_t)((rr * 4 + pl) ^ ks);
                const uint32_t s1 = (uint32_t)((rr * 4 + pl + 1) ^ ks);
                const uint32_t fb = base + (uint32_t)((ks * 8 + mf) * 32) * 16 + hi * 8;
                sts64(fb + s0 * 16, h0, h1);
                sts64(fb + s1 * 16, h2, h3);
            }
        } else {
            float4 blo, bhi;
            int mf = 0, rr = 0, q = 0;
            if (t < 128) {
                const int pr = t >> 1;
                q = t & 1; mf = pr >> 3; rr = pr & 7;
                const int rlo = rB + mf * 16 + rr;
                blo = *reinterpret_cast<const float4*>(batches + (size_t)rlo * DB + q * 4);
                bhi = *reinterpret_cast<const float4*>(batches + (size_t)(rlo + 8) * DB + q * 4);
            }
            for (int i = t; i < 2048; i += 256) sf[i] = 0;
            __syncthreads();
            if (t < 128) {
                const uint32_t h0 = h2pack(blo.x, blo.y);
                const uint32_t h1 = h2pack(bhi.x, bhi.y);
                const uint32_t h2 = h2pack(blo.z, blo.w);
                const uint32_t h3 = h2pack(bhi.z, bhi.w);
                const int pl = 2 * q;
                const uint32_t fb = base + (uint32_t)(mf * 32) * 16;
                sts64(fb + (uint32_t)(rr * 4 + pl) * 16, h0, h1);
                sts64(fb + (uint32_t)(rr * 4 + pl + 1) * 16, h2, h3);
            }
        }
        __syncthreads();
        uint4* dst = reinterpret_cast<uint4*>(
            g_Afrag + ((size_t)(b * 32 + y) * NSLAB + s) * IMG_BYTES);
        const uint4* src = reinterpret_cast<const uint4*>(sf);
        dst[t] = src[t];
        dst[256 + t] = src[256 + t];
    } else {
        // ---------------- W tile ----------------
        const int cbi = y - 32;
        const float* Wb = W + (size_t)b * KD * MD + cbi * 128;
        if (s < 129) {
            float4 w0[2], w1[2];
#pragma unroll
            for (int p = 0; p < 2; p++) {
                const int unit = p * 256 + t;
                const int kp = unit >> 5, n0 = (unit & 31) * 4;
                const int k = k0 + kp * 2;
                w0[p] = *reinterpret_cast<const float4*>(Wb + (size_t)k * MD + n0);
                w1[p] = *reinterpret_cast<const float4*>(Wb + (size_t)(k + 1) * MD + n0);
            }
#pragma unroll
            for (int p = 0; p < 2; p++) {
                const int unit = p * 256 + t;
                const int kp = unit >> 5, n0 = (unit & 31) * 4;
                const int ks = kp >> 3, kpi = kp & 7;
                const int tk = kpi & 3, hi = kpi >> 2;
                const uint32_t h[4] = {h2pack(w0[p].x, w1[p].x), h2pack(w0[p].y, w1[p].y),
                                       h2pack(w0[p].z, w1[p].z), h2pack(w0[p].w, w1[p].w)};
#pragma unroll
                for (int i = 0; i < 4; i++) {
                    const int n = n0 + i, col = n & 7, nf = n >> 3, np = nf >> 1;
                    const int reg = (nf & 1) * 2 + hi;
                    const int slot = (col * 4 + tk) ^ np;
                    sts32(base + (uint32_t)(((ks * 8 + np) * 32 + slot) * 16 + reg * 4),
                          h[i]);
                }
            }
        } else {
            float4 w0, w1;
            int kp = 0, n0 = 0;
            if (t < 128) {
                kp = t >> 5; n0 = (t & 31) * 4;
                const int k = k0 + kp * 2;
                w0 = *reinterpret_cast<const float4*>(Wb + (size_t)k * MD + n0);
                w1 = *reinterpret_cast<const float4*>(Wb + (size_t)(k + 1) * MD + n0);
            }
            for (int i = t; i < 2048; i += 256) sf[i] = 0;
            __syncthreads();
            if (t < 128) {
                const int tk = kp & 3;
                const uint32_t h[4] = {h2pack(w0.x, w1.x), h2pack(w0.y, w1.y),
                                       h2pack(w0.z, w1.z), h2pack(w0.w, w1.w)};
#pragma unroll
                for (int i = 0; i < 4; i++) {
                    const int n = n0 + i, col = n & 7, nf = n >> 3, np = nf >> 1;
                    const int reg = (nf & 1) * 2;
                    const int slot = (col * 4 + tk) ^ np;
                    sts32(base + (uint32_t)((np * 32 + slot) * 16 + reg * 4), h[i]);
                }
            }
        }
        __syncthreads();
        uint4* dst = reinterpret_cast<uint4*>(
            g_Wfrag + ((size_t)(b * 4 + cbi) * NSLAB + s) * IMG_BYTES);
        const uint4* src = reinterpret_cast<const uint4*>(sf);
        dst[t] = src[t];
        dst[256 + t] = src[256 + t];
    }
}

// ===== main: 4 warps/CTA, 64x64 warp tiles (halved LDS amplification), 3-buffer ring =====
__global__ void __launch_bounds__(128, 2)
ib_main(const float* __restrict__ bias, float* __restrict__ out)
{
    extern __shared__ char smem[];
    const uint32_t sb = smem_u32(smem);
    const int t    = threadIdx.x;
    const int lane = t & 31;
    const int wid  = t >> 5;         // 0..3
    const int wm   = wid & 1;        // 64 rows each
    const int wn   = wid >> 1;       // 64 cols each
    const int cbi  = blockIdx.x;
    const int rt   = blockIdx.y;
    const int b    = blockIdx.z;
    const int rB   = rt * 128;
    const int cB   = cbi * 128;

    const uint8_t* gA = g_Afrag + (size_t)(b * 32 + rt) * NSLAB * IMG_BYTES;
    const uint8_t* gW = g_Wfrag + (size_t)(b * 4 + cbi) * NSLAB * IMG_BYTES;

    float acc[4][8][4];
#pragma unroll
    for (int m = 0; m < 4; m++)
#pragma unroll
        for (int n = 0; n < 8; n++)
#pragma unroll
            for (int q = 0; q < 4; q++) acc[m][n][q] = 0.f;

    // stage layout: [A(img0) 8K][A(img1) 8K][B(img0) 8K][B(img1) 8K]
    // 128 threads: each half (16KB) = 8 chunks of 2KB (one cp16 per thread per chunk)
    auto cp_half = [&](int p, int half) {   // half 0 = A images, half 1 = B images
        const uint32_t buf = sb + (uint32_t)((p % NBUF) * STAGE_BYTES)
                           + (uint32_t)half * 2 * IMG_BYTES;
        const uint8_t* src = (half == 0 ? gA : gW) + (size_t)(2 * p) * IMG_BYTES;
        const uint32_t off = (uint32_t)t * 16;
#pragma unroll
        for (int c = 0; c < 8; c++)
            cp16(buf + c * 2048 + off, src + c * 2048 + off);
    };

    auto consume = [&](uint32_t buf, int img, int ks) {
        const uint32_t abase = buf + (uint32_t)img * IMG_BYTES;
        const uint32_t bbase = buf + 2 * IMG_BYTES + (uint32_t)img * IMG_BYTES;
        uint32_t afr[4][4], bfr[4][4];
#pragma unroll
        for (int mi = 0; mi < 4; mi++) {
            const int mf = wm * 4 + mi;
            lds128(abase + (uint32_t)(((ks * 8 + mf) * 32 + (lane ^ ks)) * 16), afr[mi]);
        }
#pragma unroll
        for (int pp = 0; pp < 4; pp++) {
            const int np = wn * 4 + pp;
            lds128(bbase + (uint32_t)(((ks * 8 + np) * 32 + (lane ^ np)) * 16), bfr[pp]);
        }
#pragma unroll
        for (int mi = 0; mi < 4; mi++)
#pragma unroll
            for (int pp = 0; pp < 4; pp++) {
                mma16(acc[mi][2 * pp],     afr[mi], bfr[pp][0], bfr[pp][1]);
                mma16(acc[mi][2 * pp + 1], afr[mi], bfr[pp][2], bfr[pp][3]);
            }
    };

    // prologue: 2 pair-stages in flight
    cp_half(0, 0); cp_half(0, 1); CP_COMMIT();
    cp_half(1, 0); cp_half(1, 1); CP_COMMIT();

    for (int p = 0; p < NPAIR; p++) {
        CP_WAIT1();               // stage p resident (<=1 newer group pending)
        __syncthreads();          // all warps done with stage p-1's buffer
        const uint32_t buf = sb + (uint32_t)((p % NBUF) * STAGE_BYTES);
        // interleave next-stage cp issue between consume steps (smooths LSU pressure)
        consume(buf, 0, 0);
        if (p + 2 < NPAIR) cp_half(p + 2, 0);
        consume(buf, 0, 1);
        if (p + 2 < NPAIR) cp_half(p + 2, 1);
        CP_COMMIT();              // exactly one group per iteration
        consume(buf, 1, 0);
        consume(buf, 1, 1);
    }

    // -------- epilogue: bias + LeakyReLU --------
    const int g  = lane >> 2;
    const int tq = lane & 3;
#pragma unroll
    for (int mi = 0; mi < 4; mi++) {
        const int r0 = rB + wm * 64 + mi * 16 + g;
#pragma unroll
        for (int nf = 0; nf < 8; nf++) {
            const int col = cB + wn * 64 + nf * 8 + tq * 2;
            const float2 bv = *reinterpret_cast<const float2*>(bias + b * MD + col);
            float v0 = acc[mi][nf][0] + bv.x;
            float v1 = acc[mi][nf][1] + bv.y;
            float v2 = acc[mi][nf][2] + bv.x;
            float v3 = acc[mi][nf][3] + bv.y;
            v0 = (v0 >= 0.f) ? v0 : ALPHA * v0;
            v1 = (v1 >= 0.f) ? v1 : ALPHA * v1;
            v2 = (v2 >= 0.f) ? v2 : ALPHA * v2;
            v3 = (v3 >= 0.f) ? v3 : ALPHA * v3;
            *reinterpret_cast<float2*>(out + (size_t)r0 * (NB * MD) + b * MD + col)
                = make_float2(v0, v1);
            *reinterpret_cast<float2*>(out + (size_t)(r0 + 8) * (NB * MD) + b * MD + col)
                = make_float2(v2, v3);
        }
    }
}

} // namespace

extern "C" void kernel_launch(void* const* d_in, const int* in_sizes, int n_in,
                              void* d_out, int out_size)
{
    const float*    x       = (const float*)d_in[0];
    const uint32_t* mask    = (const uint32_t*)d_in[1];
    const float*    embed   = (const float*)d_in[2];
    const float*    batches = (const float*)d_in[3];
    const float*    mean    = (const float*)d_in[4];
    const float*    W       = (const float*)d_in[5];
    const float*    bias    = (const float*)d_in[6];
    float*          out     = (float*)d_out;

    prep_all<<<dim3(NSLAB, 36, NB), 256>>>(x, mask, embed, batches, mean, W);

    cudaFuncSetAttribute(ib_main, cudaFuncAttributeMaxDynamicSharedMemorySize, SMEM_MAIN);
    ib_main<<<dim3(4, 32, NB), 128, SMEM_MAIN>>>(bias, out);
}